// round 9
// baseline (speedup 1.0000x reference)
#include <cuda_runtime.h>
#include <math.h>

// Problem constants (fixed by the reference)
#define POOL   100
#define NTASKS 10
#define NB_PT  (POOL / NTASKS)       // 10
#define PLEN   8
#define EMBD   768
#define BATCH  512
#define ED4    (EMBD / 4)            // 192

#define SIM_G       4                // batch groups in sim grid.x
#define ROWS_PER_B  (BATCH / SIM_G)  // 128 rows per block
#define ROWS_PER_W  (ROWS_PER_B / 8) // 16 rows per warp
#define COPY_BLOCKS 2560
#define BPB         4                // batch rows per pmt block
#define PMT_BLOCKS  (BATCH / BPB)    // 128
#define OUT_PER_T   ((PLEN * ED4) / 256)   // 6 float4 outputs per thread

// Scratch (allocation-free per harness rules)
__device__ float g_sim[BATCH * POOL];

// ---------------------------------------------------------------------------
// Kernel 1: fused diag + sim. grid=(SIM_G, POOL), block=256.
// diag[k] computed ONCE per block in smem (e_p traffic: 400*24KB = 9.4 MB).
// ---------------------------------------------------------------------------
__global__ void sim_kernel(const float* __restrict__ x_querry,
                           const float* __restrict__ e_a,
                           const float* __restrict__ e_p,
                           const int*   __restrict__ task_id_p) {
    const int task_end = (*task_id_p + 1) * NB_PT;
    const int k = blockIdx.y;
    if (k >= task_end) return;

    __shared__ float s_diag[EMBD];
    __shared__ float s_ea[EMBD];

    const float* epk = e_p + (size_t)k * PLEN * EMBD;
    for (int d = threadIdx.x; d < EMBD; d += 256) {
        float acc = 0.f;
#pragma unroll
        for (int l = 0; l < PLEN; l++) {
            float v = epk[l * EMBD + d];
            acc += v * v;
        }
        s_diag[d] = acc;
        s_ea[d]   = e_a[(size_t)k * EMBD + d];
    }
    __syncthreads();

    const int warp = threadIdx.x >> 5;
    const int lane = threadIdx.x & 31;
    const int row = POOL - task_end + k;
    const int b_base = blockIdx.x * ROWS_PER_B + warp * ROWS_PER_W;

    const float4* ea4 = (const float4*)s_ea;
    const float4* dg4 = (const float4*)s_diag;

    for (int rr = 0; rr < ROWS_PER_W; rr++) {
        const int b = b_base + rr;
        const float4* xq4 = (const float4*)(x_querry +
                            ((size_t)b * POOL + row) * EMBD);
        float s1 = 0.f, s2 = 0.f, s3 = 0.f;
#pragma unroll
        for (int j = 0; j < ED4 / 32; j++) {   // 6 iterations
            int idx = lane + j * 32;
            float4 x = xq4[idx];
            float4 e = ea4[idx];
            float4 g = dg4[idx];
            float a, aa;
            a = x.x * e.x; aa = a * a; s3 += aa; s1 += aa * g.x; s2 += aa * g.x * g.x;
            a = x.y * e.y; aa = a * a; s3 += aa; s1 += aa * g.y; s2 += aa * g.y * g.y;
            a = x.z * e.z; aa = a * a; s3 += aa; s1 += aa * g.z; s2 += aa * g.z * g.z;
            a = x.w * e.w; aa = a * a; s3 += aa; s1 += aa * g.w; s2 += aa * g.w * g.w;
        }
#pragma unroll
        for (int o = 16; o > 0; o >>= 1) {
            s1 += __shfl_down_sync(0xFFFFFFFFu, s1, o);
            s2 += __shfl_down_sync(0xFFFFFFFFu, s2, o);
            s3 += __shfl_down_sync(0xFFFFFFFFu, s3, o);
        }
        if (lane == 0) {
            const float eps = 1e-12f;
            float n1 = fmaxf(sqrtf(s2), eps);
            float n2 = fmaxf(sqrtf(s3), eps);
            g_sim[(size_t)b * POOL + k] = s1 / (n1 * n2);
        }
    }
}

// ---------------------------------------------------------------------------
// Kernel 2: pmt — 4 batch rows per block; each e_p float4 feeds 4 accums.
// (Standalone kernel: its register appetite can't hurt the copy.)
// ---------------------------------------------------------------------------
__global__ void pmt_kernel(const float* __restrict__ e_p,
                           const int*   __restrict__ task_id_p,
                           float* __restrict__ out) {
    const int task_end = (*task_id_p + 1) * NB_PT;
    const int b0 = blockIdx.x * BPB;
    const int tid = threadIdx.x;

    __shared__ float s_sim[BPB][POOL];
    for (int i = tid; i < BPB * POOL; i += 256)
        s_sim[i / POOL][i % POOL] = g_sim[(size_t)(b0 + i / POOL) * POOL + (i % POOL)];
    __syncthreads();

    const float4* ep4 = (const float4*)e_p;

    float4 acc[BPB][OUT_PER_T];
#pragma unroll
    for (int bs = 0; bs < BPB; bs++)
#pragma unroll
        for (int j = 0; j < OUT_PER_T; j++)
            acc[bs][j] = make_float4(0.f, 0.f, 0.f, 0.f);

    for (int kk = 0; kk < task_end; kk++) {
        float sv[BPB];
#pragma unroll
        for (int bs = 0; bs < BPB; bs++) sv[bs] = s_sim[bs][kk];
#pragma unroll
        for (int j = 0; j < OUT_PER_T; j++) {
            int idx = tid + j * 256;
            int l  = idx / ED4;
            int d4 = idx % ED4;
            float4 v = ep4[((size_t)kk * PLEN + l) * ED4 + d4];
#pragma unroll
            for (int bs = 0; bs < BPB; bs++) {
                acc[bs][j].x += sv[bs] * v.x;
                acc[bs][j].y += sv[bs] * v.y;
                acc[bs][j].z += sv[bs] * v.z;
                acc[bs][j].w += sv[bs] * v.w;
            }
        }
    }

    const size_t KEY4 = (size_t)BATCH * (PLEN / 2) * ED4;
#pragma unroll
    for (int j = 0; j < OUT_PER_T; j++) {
        int idx = tid + j * 256;
        int l  = idx / ED4;
        int d4 = idx % ED4;
#pragma unroll
        for (int bs = 0; bs < BPB; bs++) {
            int b = b0 + bs;
            float4* o4;
            if (l < PLEN / 2)
                o4 = (float4*)out + ((size_t)b * (PLEN / 2) + l) * ED4 + d4;
            else
                o4 = (float4*)out + KEY4 +
                     ((size_t)b * (PLEN / 2) + (l - PLEN / 2)) * ED4 + d4;
            *o4 = acc[bs][j];
        }
    }
}

// ---------------------------------------------------------------------------
// Kernel 3: pure streaming copy (measured 89.9 us @ 6331 GB/s) — untouched.
// ---------------------------------------------------------------------------
__global__ void __launch_bounds__(256) copy_kernel(
        const float* __restrict__ x_block,
        float* __restrict__ out,
        size_t xb_float4s) {
    const float4* src = (const float4*)x_block;
    float4* dst = (float4*)(out + (size_t)BATCH * PLEN * EMBD);

    const size_t stride = (size_t)COPY_BLOCKS * 256;
    size_t i = (size_t)blockIdx.x * 256 + threadIdx.x;

    for (; i + 3 * stride < xb_float4s; i += 4 * stride) {
        float4 v0 = __ldcs(src + i);
        float4 v1 = __ldcs(src + i + stride);
        float4 v2 = __ldcs(src + i + 2 * stride);
        float4 v3 = __ldcs(src + i + 3 * stride);
        __stcs(dst + i,              v0);
        __stcs(dst + i + stride,     v1);
        __stcs(dst + i + 2 * stride, v2);
        __stcs(dst + i + 3 * stride, v3);
    }
    for (; i < xb_float4s; i += stride)
        __stcs(dst + i, __ldcs(src + i));
}

// ---------------------------------------------------------------------------
// Launch — three clean serial kernels on the capture stream.
// Inputs (metadata order): x_querry, x_block, e_a, e_p, idx, task_id
// ---------------------------------------------------------------------------
extern "C" void kernel_launch(void* const* d_in, const int* in_sizes, int n_in,
                              void* d_out, int out_size) {
    const float* x_querry = (const float*)d_in[0];
    const float* x_block  = (const float*)d_in[1];
    const float* e_a      = (const float*)d_in[2];
    const float* e_p      = (const float*)d_in[3];
    const int*   task_id  = (const int*)d_in[5];
    float* out = (float*)d_out;

    dim3 sim_grid(SIM_G, POOL);
    sim_kernel<<<sim_grid, 256>>>(x_querry, e_a, e_p, task_id);

    pmt_kernel<<<PMT_BLOCKS, 256>>>(e_p, task_id, out);

    size_t xb_float4s = (size_t)in_sizes[1] / 4;
    copy_kernel<<<COPY_BLOCKS, 256>>>(x_block, out, xb_float4s);
}

// round 10
// speedup vs baseline: 1.1370x; 1.1370x over previous
#include <cuda_runtime.h>
#include <math.h>

// Problem constants (fixed by the reference)
#define POOL   100
#define NTASKS 10
#define NB_PT  (POOL / NTASKS)       // 10
#define PLEN   8
#define EMBD   768
#define BATCH  512
#define ED4    (EMBD / 4)            // 192

// sim: 1600 blocks — the parallelism/redundancy balance point
#define SIM_G       16
#define ROWS_PER_B  (BATCH / SIM_G)      // 32 rows per block
#define ROWS_PER_W  (ROWS_PER_B / 8)     // 4 rows per warp

// pmt: 512 blocks via batch-split x output-split
#define BPB         4                    // batch rows per block
#define SPLIT       4                    // output-range splits per batch group
#define PMT_THREADS 192
#define CHUNK4      ((PLEN * ED4) / SPLIT)        // 384 float4 per block
#define OUT_PER_T   (CHUNK4 / PMT_THREADS)        // 2 float4 per thread

#define COPY_BLOCKS 2560

// Scratch (allocation-free per harness rules)
__device__ float g_sim[BATCH * POOL];

// ---------------------------------------------------------------------------
// Kernel 1: fused diag + sim. grid=(16, POOL), block=256 (8 warps).
// diag[k] built once per block in smem; 4 batch rows per warp.
// ---------------------------------------------------------------------------
__global__ void sim_kernel(const float* __restrict__ x_querry,
                           const float* __restrict__ e_a,
                           const float* __restrict__ e_p,
                           const int*   __restrict__ task_id_p) {
    const int task_end = (*task_id_p + 1) * NB_PT;
    const int k = blockIdx.y;
    if (k >= task_end) return;

    __shared__ float s_diag[EMBD];
    __shared__ float s_ea[EMBD];

    const float* epk = e_p + (size_t)k * PLEN * EMBD;
    for (int d = threadIdx.x; d < EMBD; d += 256) {
        float acc = 0.f;
#pragma unroll
        for (int l = 0; l < PLEN; l++) {
            float v = epk[l * EMBD + d];
            acc += v * v;
        }
        s_diag[d] = acc;
        s_ea[d]   = e_a[(size_t)k * EMBD + d];
    }
    __syncthreads();

    const int warp = threadIdx.x >> 5;
    const int lane = threadIdx.x & 31;
    const int row = POOL - task_end + k;
    const int b_base = blockIdx.x * ROWS_PER_B + warp * ROWS_PER_W;

    const float4* ea4 = (const float4*)s_ea;
    const float4* dg4 = (const float4*)s_diag;

#pragma unroll
    for (int rr = 0; rr < ROWS_PER_W; rr++) {
        const int b = b_base + rr;
        const float4* xq4 = (const float4*)(x_querry +
                            ((size_t)b * POOL + row) * EMBD);
        float s1 = 0.f, s2 = 0.f, s3 = 0.f;
#pragma unroll
        for (int j = 0; j < ED4 / 32; j++) {   // 6 iterations
            int idx = lane + j * 32;
            float4 x = xq4[idx];
            float4 e = ea4[idx];
            float4 g = dg4[idx];
            float a, aa;
            a = x.x * e.x; aa = a * a; s3 += aa; s1 += aa * g.x; s2 += aa * g.x * g.x;
            a = x.y * e.y; aa = a * a; s3 += aa; s1 += aa * g.y; s2 += aa * g.y * g.y;
            a = x.z * e.z; aa = a * a; s3 += aa; s1 += aa * g.z; s2 += aa * g.z * g.z;
            a = x.w * e.w; aa = a * a; s3 += aa; s1 += aa * g.w; s2 += aa * g.w * g.w;
        }
#pragma unroll
        for (int o = 16; o > 0; o >>= 1) {
            s1 += __shfl_down_sync(0xFFFFFFFFu, s1, o);
            s2 += __shfl_down_sync(0xFFFFFFFFu, s2, o);
            s3 += __shfl_down_sync(0xFFFFFFFFu, s3, o);
        }
        if (lane == 0) {
            const float eps = 1e-12f;
            float n1 = fmaxf(sqrtf(s2), eps);
            float n2 = fmaxf(sqrtf(s3), eps);
            g_sim[(size_t)b * POOL + k] = s1 / (n1 * n2);
        }
    }
}

// ---------------------------------------------------------------------------
// Kernel 2: pmt. grid = (BATCH/BPB) * SPLIT = 512 blocks, 192 threads.
// Block (g, sp): batch rows [g*4, g*4+4), output float4 range
// [sp*384, (sp+1)*384). Each e_p float4 read feeds 4 batch accumulators.
// ---------------------------------------------------------------------------
__global__ void pmt_kernel(const float* __restrict__ e_p,
                           const int*   __restrict__ task_id_p,
                           float* __restrict__ out) {
    const int task_end = (*task_id_p + 1) * NB_PT;
    const int g  = blockIdx.x / SPLIT;
    const int sp = blockIdx.x % SPLIT;
    const int b0 = g * BPB;
    const int tid = threadIdx.x;

    __shared__ float s_sim[BPB][POOL];
    for (int i = tid; i < BPB * POOL; i += PMT_THREADS)
        s_sim[i / POOL][i % POOL] =
            g_sim[(size_t)(b0 + i / POOL) * POOL + (i % POOL)];
    __syncthreads();

    const float4* ep4 = (const float4*)e_p;
    const int base4 = sp * CHUNK4;   // start float4 index within (l,d4) space

    float4 acc[BPB][OUT_PER_T];
#pragma unroll
    for (int bs = 0; bs < BPB; bs++)
#pragma unroll
        for (int j = 0; j < OUT_PER_T; j++)
            acc[bs][j] = make_float4(0.f, 0.f, 0.f, 0.f);

    for (int kk = 0; kk < task_end; kk++) {
        float sv[BPB];
#pragma unroll
        for (int bs = 0; bs < BPB; bs++) sv[bs] = s_sim[bs][kk];
#pragma unroll
        for (int j = 0; j < OUT_PER_T; j++) {
            int idx = base4 + tid + j * PMT_THREADS;   // float4 idx in [0,1536)
            float4 v = ep4[(size_t)kk * PLEN * ED4 + idx];
#pragma unroll
            for (int bs = 0; bs < BPB; bs++) {
                acc[bs][j].x += sv[bs] * v.x;
                acc[bs][j].y += sv[bs] * v.y;
                acc[bs][j].z += sv[bs] * v.z;
                acc[bs][j].w += sv[bs] * v.w;
            }
        }
    }

    const size_t KEY4 = (size_t)BATCH * (PLEN / 2) * ED4;
#pragma unroll
    for (int j = 0; j < OUT_PER_T; j++) {
        int idx = base4 + tid + j * PMT_THREADS;
        int l  = idx / ED4;
        int d4 = idx % ED4;
#pragma unroll
        for (int bs = 0; bs < BPB; bs++) {
            int b = b0 + bs;
            float4* o4;
            if (l < PLEN / 2)
                o4 = (float4*)out + ((size_t)b * (PLEN / 2) + l) * ED4 + d4;
            else
                o4 = (float4*)out + KEY4 +
                     ((size_t)b * (PLEN / 2) + (l - PLEN / 2)) * ED4 + d4;
            *o4 = acc[bs][j];
        }
    }
}

// ---------------------------------------------------------------------------
// Kernel 3: pure streaming copy (measured 89.9 us @ 6331 GB/s) — untouched.
// ---------------------------------------------------------------------------
__global__ void __launch_bounds__(256) copy_kernel(
        const float* __restrict__ x_block,
        float* __restrict__ out,
        size_t xb_float4s) {
    const float4* src = (const float4*)x_block;
    float4* dst = (float4*)(out + (size_t)BATCH * PLEN * EMBD);

    const size_t stride = (size_t)COPY_BLOCKS * 256;
    size_t i = (size_t)blockIdx.x * 256 + threadIdx.x;

    for (; i + 3 * stride < xb_float4s; i += 4 * stride) {
        float4 v0 = __ldcs(src + i);
        float4 v1 = __ldcs(src + i + stride);
        float4 v2 = __ldcs(src + i + 2 * stride);
        float4 v3 = __ldcs(src + i + 3 * stride);
        __stcs(dst + i,              v0);
        __stcs(dst + i + stride,     v1);
        __stcs(dst + i + 2 * stride, v2);
        __stcs(dst + i + 3 * stride, v3);
    }
    for (; i < xb_float4s; i += stride)
        __stcs(dst + i, __ldcs(src + i));
}

// ---------------------------------------------------------------------------
// Launch — three clean serial kernels on the capture stream.
// Inputs (metadata order): x_querry, x_block, e_a, e_p, idx, task_id
// ---------------------------------------------------------------------------
extern "C" void kernel_launch(void* const* d_in, const int* in_sizes, int n_in,
                              void* d_out, int out_size) {
    const float* x_querry = (const float*)d_in[0];
    const float* x_block  = (const float*)d_in[1];
    const float* e_a      = (const float*)d_in[2];
    const float* e_p      = (const float*)d_in[3];
    const int*   task_id  = (const int*)d_in[5];
    float* out = (float*)d_out;

    dim3 sim_grid(SIM_G, POOL);
    sim_kernel<<<sim_grid, 256>>>(x_querry, e_a, e_p, task_id);

    pmt_kernel<<<(BATCH / BPB) * SPLIT, PMT_THREADS>>>(e_p, task_id, out);

    size_t xb_float4s = (size_t)in_sizes[1] / 4;
    copy_kernel<<<COPY_BLOCKS, 256>>>(x_block, out, xb_float4s);
}

// round 11
// speedup vs baseline: 1.1649x; 1.0246x over previous
#include <cuda_runtime.h>
#include <math.h>

// Problem constants (fixed by the reference)
#define POOL   100
#define NTASKS 10
#define NB_PT  (POOL / NTASKS)       // 10
#define PLEN   8
#define EMBD   768
#define BATCH  512
#define ED4    (EMBD / 4)            // 192

#define PMT_BLOCKS  BATCH            // 512 (mega, first)
#define COPY_BLOCKS 2560             // (mega, after pmt)

// Scratch (allocation-free per harness rules)
__device__ float g_sim[BATCH * POOL];
__device__ float g_w1[POOL * EMBD];  // e^2 * diag
__device__ float g_w2[POOL * EMBD];  // e^2 * diag^2
__device__ float g_w3[POOL * EMBD];  // e^2

// ---------------------------------------------------------------------------
// Kernel 1: wvec — fully parallel, no task_end gating, no phases.
//   w3 = e_a^2 ; w1 = e_a^2*diag ; w2 = e_a^2*diag^2, diag = sum_l e_p^2.
//   19200 threads, 8 independent loads each (MLP=8).
// ---------------------------------------------------------------------------
__global__ void wvec_kernel(const float* __restrict__ e_a,
                            const float* __restrict__ e_p) {
    int i = blockIdx.x * blockDim.x + threadIdx.x;   // over POOL*ED4
    if (i >= POOL * ED4) return;
    const float4* ep4 = (const float4*)e_p;
    int k  = i / ED4;
    int d4 = i % ED4;

    float4 g = make_float4(0.f, 0.f, 0.f, 0.f);
#pragma unroll
    for (int l = 0; l < PLEN; l++) {
        float4 v = ep4[((size_t)k * PLEN + l) * ED4 + d4];
        g.x += v.x * v.x; g.y += v.y * v.y;
        g.z += v.z * v.z; g.w += v.w * v.w;
    }
    float4 e = ((const float4*)e_a)[i];
    float4 e2  = make_float4(e.x * e.x, e.y * e.y, e.z * e.z, e.w * e.w);
    float4 w1  = make_float4(e2.x * g.x, e2.y * g.y, e2.z * g.z, e2.w * g.w);
    float4 w2  = make_float4(w1.x * g.x, w1.y * g.y, w1.z * g.z, w1.w * g.w);
    ((float4*)g_w3)[i] = e2;
    ((float4*)g_w1)[i] = w1;
    ((float4*)g_w2)[i] = w2;
}

// ---------------------------------------------------------------------------
// Kernel 2: sim — block per b (ALL 512 blocks active for any task_id).
//   Warp w handles k = w, w+8, ... No smem, no sync, pure streaming:
//   sim[b,k] = Sx2w1 / (sqrt(Sx2w2)*sqrt(Sx2w3)),  x2 = xq^2.
// ---------------------------------------------------------------------------
__global__ void __launch_bounds__(256) sim_kernel(
        const float* __restrict__ x_querry,
        const int*   __restrict__ task_id_p) {
    const int task_end = (*task_id_p + 1) * NB_PT;
    const int b    = blockIdx.x;
    const int warp = threadIdx.x >> 5;
    const int lane = threadIdx.x & 31;

    const float4* w14 = (const float4*)g_w1;
    const float4* w24 = (const float4*)g_w2;
    const float4* w34 = (const float4*)g_w3;

    for (int k = warp; k < task_end; k += 8) {
        const int row = POOL - task_end + k;
        const float4* xq4 = (const float4*)(x_querry +
                            ((size_t)b * POOL + row) * EMBD);
        const size_t kb = (size_t)k * ED4;

        float s1 = 0.f, s2 = 0.f, s3 = 0.f;
#pragma unroll
        for (int j = 0; j < ED4 / 32; j++) {   // 6 iterations
            int idx = lane + j * 32;
            float4 x  = xq4[idx];
            float4 a1 = w14[kb + idx];
            float4 a2 = w24[kb + idx];
            float4 a3 = w34[kb + idx];
            float xx;
            xx = x.x * x.x; s1 += xx * a1.x; s2 += xx * a2.x; s3 += xx * a3.x;
            xx = x.y * x.y; s1 += xx * a1.y; s2 += xx * a2.y; s3 += xx * a3.y;
            xx = x.z * x.z; s1 += xx * a1.z; s2 += xx * a2.z; s3 += xx * a3.z;
            xx = x.w * x.w; s1 += xx * a1.w; s2 += xx * a2.w; s3 += xx * a3.w;
        }
#pragma unroll
        for (int o = 16; o > 0; o >>= 1) {
            s1 += __shfl_down_sync(0xFFFFFFFFu, s1, o);
            s2 += __shfl_down_sync(0xFFFFFFFFu, s2, o);
            s3 += __shfl_down_sync(0xFFFFFFFFu, s3, o);
        }
        if (lane == 0) {
            const float eps = 1e-12f;
            float n1 = fmaxf(sqrtf(s2), eps);
            float n2 = fmaxf(sqrtf(s3), eps);
            g_sim[(size_t)b * POOL + k] = s1 / (n1 * n2);
        }
    }
}

// ---------------------------------------------------------------------------
// Kernel 3: mega — round-2 proven config (95.7 us, regs 40):
//   blocks [0,512): pmt einsum; blocks [512, 3072): streaming copy.
// ---------------------------------------------------------------------------
__global__ void __launch_bounds__(256) mega_kernel(
        const float* __restrict__ e_p,
        const float* __restrict__ x_block,
        const int*   __restrict__ task_id_p,
        float* __restrict__ out,
        size_t xb_float4s) {
    if (blockIdx.x < PMT_BLOCKS) {
        // ---- einsum: int_pmt[b,l,d] = sum_k sim[b,k] * e_p[k,l,d] ----
        const int task_end = (*task_id_p + 1) * NB_PT;
        const int b = blockIdx.x;

        __shared__ float s_sim[POOL];
        if (threadIdx.x < POOL)
            s_sim[threadIdx.x] = g_sim[(size_t)b * POOL + threadIdx.x];
        __syncthreads();

        const float4* ep4 = (const float4*)e_p;
        const size_t KEY4 = (size_t)BATCH * (PLEN / 2) * ED4;

        for (int idx = threadIdx.x; idx < PLEN * ED4; idx += 256) {
            int l  = idx / ED4;
            int d4 = idx % ED4;
            float4 acc = make_float4(0.f, 0.f, 0.f, 0.f);
            for (int kk = 0; kk < task_end; kk++) {
                float s  = s_sim[kk];
                float4 v = ep4[((size_t)kk * PLEN + l) * ED4 + d4];
                acc.x += s * v.x; acc.y += s * v.y;
                acc.z += s * v.z; acc.w += s * v.w;
            }
            float4* o4;
            if (l < PLEN / 2)
                o4 = (float4*)out + ((size_t)b * (PLEN / 2) + l) * ED4 + d4;
            else
                o4 = (float4*)out + KEY4 +
                     ((size_t)b * (PLEN / 2) + (l - PLEN / 2)) * ED4 + d4;
            *o4 = acc;
        }
    } else {
        // ---- streaming copy: x_block -> out tail ----
        const float4* src = (const float4*)x_block;
        float4* dst = (float4*)(out + (size_t)BATCH * PLEN * EMBD);

        const size_t stride = (size_t)COPY_BLOCKS * 256;
        size_t i = (size_t)(blockIdx.x - PMT_BLOCKS) * 256 + threadIdx.x;

        for (; i + 3 * stride < xb_float4s; i += 4 * stride) {
            float4 v0 = __ldcs(src + i);
            float4 v1 = __ldcs(src + i + stride);
            float4 v2 = __ldcs(src + i + 2 * stride);
            float4 v3 = __ldcs(src + i + 3 * stride);
            __stcs(dst + i,              v0);
            __stcs(dst + i + stride,     v1);
            __stcs(dst + i + 2 * stride, v2);
            __stcs(dst + i + 3 * stride, v3);
        }
        for (; i < xb_float4s; i += stride)
            __stcs(dst + i, __ldcs(src + i));
    }
}

// ---------------------------------------------------------------------------
// Launch — three serial kernels: wvec -> sim -> mega(pmt+copy).
// Inputs (metadata order): x_querry, x_block, e_a, e_p, idx, task_id
// ---------------------------------------------------------------------------
extern "C" void kernel_launch(void* const* d_in, const int* in_sizes, int n_in,
                              void* d_out, int out_size) {
    const float* x_querry = (const float*)d_in[0];
    const float* x_block  = (const float*)d_in[1];
    const float* e_a      = (const float*)d_in[2];
    const float* e_p      = (const float*)d_in[3];
    const int*   task_id  = (const int*)d_in[5];
    float* out = (float*)d_out;

    wvec_kernel<<<(POOL * ED4 + 255) / 256, 256>>>(e_a, e_p);

    sim_kernel<<<BATCH, 256>>>(x_querry, task_id);

    size_t xb_float4s = (size_t)in_sizes[1] / 4;
    mega_kernel<<<PMT_BLOCKS + COPY_BLOCKS, 256>>>(
        e_p, x_block, task_id, out, xb_float4s);
}